// round 1
// baseline (speedup 1.0000x reference)
#include <cuda_runtime.h>
#include <cuda_bf16.h>
#include <cstdint>

// Problem constants
#define Bb 4
#define Nn 16384
#define Cc 128
#define Mm 1024
#define Kk 32
#define COLSX (Bb*Mm*Kk)          // 131072
#define R2c 0.16f
#define XK 136                     // padded input-channel dim for GEMM1 (131 -> 136)

// -------------------- scratch (__device__ globals; no allocations) ---------
__device__ float g_featT[(size_t)Bb*Nn*Cc];        // (B,N,C) transposed features
__device__ float g_newxyz[Bb*Mm*3];
__device__ int   g_idx[Bb*Mm*Kk];
__device__ float g_X[(size_t)COLSX*XK];            // grouped input, row per col
__device__ float g_W1p[XK*128];                    // W packed [k][cout]
__device__ float g_W2p[128*128];
__device__ float g_W3p[128*256];
__device__ float g_Y1[(size_t)128*COLSX];
__device__ float g_Y2[(size_t)128*COLSX];
__device__ float g_Y3[(size_t)256*COLSX];
__device__ float2 g_part[256*8];
__device__ float2 g_aff[256];

// -------------------- helpers ---------------------------------------------
__device__ __forceinline__ unsigned long long pack2(float lo, float hi){
    unsigned long long r;
    asm("mov.b64 %0, {%1,%2};" : "=l"(r) : "f"(lo), "f"(hi));
    return r;
}
__device__ __forceinline__ float2 unpack2(unsigned long long v){
    float2 r;
    asm("mov.b64 {%0,%1}, %2;" : "=f"(r.x), "=f"(r.y) : "l"(v));
    return r;
}
__device__ __forceinline__ void fma2(unsigned long long &d, unsigned long long a, unsigned long long b){
    asm("fma.rn.f32x2 %0, %1, %2, %3;" : "=l"(d) : "l"(a), "l"(b), "l"(d));
}

// -------------------- 1. transpose features (B,C,N)->(B,N,C) ---------------
__global__ void transpose_kernel(const float* __restrict__ f){
    __shared__ float tile[32][33];
    const int b  = blockIdx.z;
    const int c0 = blockIdx.y << 5;
    const int n0 = blockIdx.x << 5;
    const int tx = threadIdx.x, ty = threadIdx.y;
    #pragma unroll
    for (int j = 0; j < 32; j += 8)
        tile[ty + j][tx] = f[((size_t)(b*Cc + c0 + ty + j))*Nn + n0 + tx];
    __syncthreads();
    #pragma unroll
    for (int j = 0; j < 32; j += 8)
        g_featT[((size_t)(b*Nn + n0 + ty + j))*Cc + c0 + tx] = tile[tx][ty + j];
}

// -------------------- 2. weight prep (transpose + pad/reorder W1) ----------
__global__ void prepw_kernel(const float* __restrict__ w1, const float* __restrict__ w2,
                             const float* __restrict__ w3){
    int e = blockIdx.x*256 + threadIdx.x;
    if (e < XK*128){
        int kk = e >> 7, o = e & 127;
        float v = 0.f;
        if (kk < 3) v = w1[o*131 + kk];
        else if (kk >= 4 && kk < 132) v = w1[o*131 + kk - 1];
        g_W1p[e] = v;                       // [kk][o]
    }
    if (e < 128*128){
        int kk = e >> 7, o = e & 127;
        g_W2p[e] = w2[o*128 + kk];
    }
    if (e < 128*256){
        int kk = e >> 8, o = e & 255;
        g_W3p[e] = w3[o*128 + kk];
    }
}

// -------------------- 3. new_xyz gather (also writes output head) ----------
__global__ void newxyz_kernel(const float* __restrict__ xyz, const int* __restrict__ indices,
                              float* __restrict__ out){
    int t = blockIdx.x*256 + threadIdx.x;
    if (t >= Bb*Mm) return;
    int b = t >> 10;
    int i = indices[t];
    const float* p = xyz + ((size_t)b*Nn + i)*3;
    float x = p[0], y = p[1], z = p[2];
    g_newxyz[t*3+0] = x; g_newxyz[t*3+1] = y; g_newxyz[t*3+2] = z;
    out[t*3+0] = x; out[t*3+1] = y; out[t*3+2] = z;
}

// -------------------- 4. ball query (warp per query, ordered selection) ----
__global__ void ballquery_kernel(const float* __restrict__ xyz){
    const int warp = (blockIdx.x*blockDim.x + threadIdx.x) >> 5;
    const int lane = threadIdx.x & 31;
    if (warp >= Bb*Mm) return;
    const int b = warp >> 10;
    const int qbase = warp*Kk;
    const float qx = g_newxyz[warp*3+0];
    const float qy = g_newxyz[warp*3+1];
    const float qz = g_newxyz[warp*3+2];
    const float* base_p = xyz + (size_t)b*Nn*3;

    int cnt = 0;
    int first = 0;
    bool found = false;
    for (int base = 0; base < Nn; base += 32){
        if (cnt >= Kk) break;
        int n = base + lane;
        float px = base_p[n*3+0], py = base_p[n*3+1], pz = base_p[n*3+2];
        float dx = __fadd_rn(qx, -px), dy = __fadd_rn(qy, -py), dz = __fadd_rn(qz, -pz);
        float d2 = __fadd_rn(__fadd_rn(__fmul_rn(dx,dx), __fmul_rn(dy,dy)), __fmul_rn(dz,dz));
        bool w = d2 < R2c;
        unsigned mask = __ballot_sync(0xffffffffu, w);
        if (!found && mask){ first = base + __ffs(mask) - 1; found = true; }
        int pre = __popc(mask & ((1u << lane) - 1u));
        if (w && cnt + pre < Kk) g_idx[qbase + cnt + pre] = n;
        cnt += __popc(mask);
    }
    if (cnt > Kk) cnt = Kk;
    if (lane >= cnt) g_idx[qbase + lane] = first;   // first==0 when none found (matches ref)
}

// -------------------- 5. build grouped X (warp per column) -----------------
__global__ void buildx_kernel(const float* __restrict__ xyz){
    const int warp = (blockIdx.x*blockDim.x + threadIdx.x) >> 5;
    const int lane = threadIdx.x & 31;
    if (warp >= COLSX) return;
    const int col = warp;
    const int b = col >> 15;
    const int m = (col >> 5) & 1023;
    const int i = g_idx[col];
    float* dst = g_X + (size_t)col*XK;
    float4 f = *(const float4*)(g_featT + ((size_t)(b*Nn + i))*Cc + lane*4);
    *(float4*)(dst + 4 + lane*4) = f;
    if (lane == 0){
        const float* p = xyz + ((size_t)b*Nn + i)*3;
        const float* q = g_newxyz + (b*Mm + m)*3;
        float4 h; h.x = p[0]-q[0]; h.y = p[1]-q[1]; h.z = p[2]-q[2]; h.w = 0.f;
        *(float4*)dst = h;
        float4 zz; zz.x = zz.y = zz.z = zz.w = 0.f;
        *(float4*)(dst + 132) = zz;
    }
}

// -------------------- 6. SGEMM (f32x2 packed FMA), 128x128 tile ------------
template<int CKT, bool FROMX, bool ACT>
__global__ __launch_bounds__(256, 2)
void gemm_kernel(const float* __restrict__ Wp, const float* __restrict__ Bsrc,
                 const float* __restrict__ bias, const float2* __restrict__ aff,
                 float* __restrict__ Y, int RT)
{
    __shared__ float As[2][8][128];
    __shared__ float Bs[2][8][128];
    const int tid = threadIdx.x;
    const int tx = tid & 15, ty = tid >> 4;
    const int cb = blockIdx.x << 7;
    const int rb = blockIdx.y << 7;

    const int a_kc  = tid >> 5;
    const int a_row = (tid & 31) << 2;
    const int x_col = tid & 127;
    const int x_kh  = (tid >> 7) << 2;   // 0 or 4

    unsigned long long acc[8][4];
    #pragma unroll
    for (int i = 0; i < 8; i++)
        #pragma unroll
        for (int j = 0; j < 4; j++) acc[i][j] = 0ull;

    auto ldgA = [&](int k0) -> float4 {
        return *(const float4*)(Wp + (size_t)(k0 + a_kc)*RT + rb + a_row);
    };
    auto ldgB = [&](int k0) -> float4 {
        if (FROMX){
            return *(const float4*)(Bsrc + (size_t)(cb + x_col)*XK + k0 + x_kh);
        } else {
            float4 v = *(const float4*)(Bsrc + (size_t)(k0 + a_kc)*COLSX + cb + a_row);
            if (ACT){
                float2 af = aff[k0 + a_kc];
                v.x = fmaxf(fmaf(af.x, v.x, af.y), 0.f);
                v.y = fmaxf(fmaf(af.x, v.y, af.y), 0.f);
                v.z = fmaxf(fmaf(af.x, v.z, af.y), 0.f);
                v.w = fmaxf(fmaf(af.x, v.w, af.y), 0.f);
            }
            return v;
        }
    };
    auto stA = [&](int buf, float4 v){ *(float4*)&As[buf][a_kc][a_row] = v; };
    auto stB = [&](int buf, float4 v){
        if (FROMX){
            Bs[buf][x_kh+0][x_col] = v.x;
            Bs[buf][x_kh+1][x_col] = v.y;
            Bs[buf][x_kh+2][x_col] = v.z;
            Bs[buf][x_kh+3][x_col] = v.w;
        } else {
            *(float4*)&Bs[buf][a_kc][a_row] = v;
        }
    };

    stA(0, ldgA(0));
    stB(0, ldgB(0));
    __syncthreads();

    const int NT = CKT/8;
    #pragma unroll 1
    for (int t = 0; t < NT; ++t){
        float4 aP, bP;
        if (t + 1 < NT){ aP = ldgA((t+1)*8); bP = ldgB((t+1)*8); }
        const int buf = t & 1;
        #pragma unroll
        for (int kc = 0; kc < 8; ++kc){
            float4 a0 = *(const float4*)&As[buf][kc][ty<<3];
            float4 a1 = *(const float4*)&As[buf][kc][(ty<<3)+4];
            ulonglong2 bv0 = *(const ulonglong2*)&Bs[buf][kc][tx<<3];
            ulonglong2 bv1 = *(const ulonglong2*)&Bs[buf][kc][(tx<<3)+4];
            unsigned long long bb0 = bv0.x, bb1 = bv0.y, bb2 = bv1.x, bb3 = bv1.y;
            float av[8] = {a0.x,a0.y,a0.z,a0.w,a1.x,a1.y,a1.z,a1.w};
            #pragma unroll
            for (int i = 0; i < 8; i++){
                unsigned long long aa = pack2(av[i], av[i]);
                fma2(acc[i][0], aa, bb0);
                fma2(acc[i][1], aa, bb1);
                fma2(acc[i][2], aa, bb2);
                fma2(acc[i][3], aa, bb3);
            }
        }
        if (t + 1 < NT){ stA(buf^1, aP); stB(buf^1, bP); __syncthreads(); }
    }

    #pragma unroll
    for (int i = 0; i < 8; i++){
        int r = rb + (ty<<3) + i;
        float bv = bias[r];
        float2 p0 = unpack2(acc[i][0]);
        float2 p1 = unpack2(acc[i][1]);
        float2 p2 = unpack2(acc[i][2]);
        float2 p3 = unpack2(acc[i][3]);
        float4 o0; o0.x = p0.x+bv; o0.y = p0.y+bv; o0.z = p1.x+bv; o0.w = p1.y+bv;
        float4 o1; o1.x = p2.x+bv; o1.y = p2.y+bv; o1.z = p3.x+bv; o1.w = p3.y+bv;
        float* dst = Y + (size_t)r*COLSX + cb + (tx<<3);
        *(float4*)dst       = o0;
        *(float4*)(dst + 4) = o1;
    }
}

// -------------------- 7. per-channel stats (deterministic partials) --------
__global__ void stats_kernel(const float* __restrict__ Y){
    const int ch = blockIdx.x, p = blockIdx.y;
    const float4* src = (const float4*)(Y + (size_t)ch*COLSX + (size_t)p*(COLSX/8));
    float s = 0.f, s2 = 0.f;
    #pragma unroll 4
    for (int i = threadIdx.x; i < (COLSX/8)/4; i += 256){
        float4 v = src[i];
        s  += v.x + v.y + v.z + v.w;
        s2 += v.x*v.x + v.y*v.y + v.z*v.z + v.w*v.w;
    }
    #pragma unroll
    for (int o = 16; o > 0; o >>= 1){
        s  += __shfl_down_sync(0xffffffffu, s,  o);
        s2 += __shfl_down_sync(0xffffffffu, s2, o);
    }
    __shared__ float rs[8], rs2[8];
    int w = threadIdx.x >> 5, l = threadIdx.x & 31;
    if (l == 0){ rs[w] = s; rs2[w] = s2; }
    __syncthreads();
    if (threadIdx.x == 0){
        float S = 0.f, S2 = 0.f;
        #pragma unroll
        for (int i = 0; i < 8; i++){ S += rs[i]; S2 += rs2[i]; }
        g_part[ch*8 + p] = make_float2(S, S2);
    }
}

__global__ void finalize_kernel(const float* __restrict__ gamma, const float* __restrict__ beta,
                                int rows){
    int c = blockIdx.x*blockDim.x + threadIdx.x;
    if (c >= rows) return;
    float s = 0.f, s2 = 0.f;
    #pragma unroll
    for (int i = 0; i < 8; i++){ float2 v = g_part[c*8 + i]; s += v.x; s2 += v.y; }
    float inv = 1.f/(float)COLSX;
    float mu  = s*inv;
    float var = fmaxf(s2*inv - mu*mu, 0.f);
    float a = gamma[c]*rsqrtf(var + 1e-5f);
    g_aff[c] = make_float2(a, beta[c] - a*mu);
}

// -------------------- 8. final affine+relu+max over K ----------------------
__global__ void finalmax_kernel(float* __restrict__ out){
    int t = blockIdx.x*256 + threadIdx.x;            // 0 .. B*256*M-1
    int m  = t & 1023;
    int co = (t >> 10) & 255;
    int b  = t >> 18;
    float2 af = g_aff[co];
    const float4* src = (const float4*)(g_Y3 + (size_t)co*COLSX) + ((size_t)(b*Mm + m))*8;
    float mx = 0.f;   // relu lower bound
    #pragma unroll
    for (int i = 0; i < 8; i++){
        float4 v = src[i];
        mx = fmaxf(mx, fmaf(af.x, v.x, af.y));
        mx = fmaxf(mx, fmaf(af.x, v.y, af.y));
        mx = fmaxf(mx, fmaf(af.x, v.z, af.y));
        mx = fmaxf(mx, fmaf(af.x, v.w, af.y));
    }
    out[Bb*Mm*3 + (((size_t)(b*256 + co)) << 10) + m] = mx;
}

// -------------------- launch ----------------------------------------------
extern "C" void kernel_launch(void* const* d_in, const int* in_sizes, int n_in,
                              void* d_out, int out_size)
{
    const float* points_xyz = (const float*)d_in[0];
    const float* features   = (const float*)d_in[1];
    const int*   indices    = (const int*)  d_in[2];
    const float* w1 = (const float*)d_in[3];
    const float* b1 = (const float*)d_in[4];
    const float* g1 = (const float*)d_in[5];
    const float* be1= (const float*)d_in[6];
    const float* w2 = (const float*)d_in[7];
    const float* b2 = (const float*)d_in[8];
    const float* g2 = (const float*)d_in[9];
    const float* be2= (const float*)d_in[10];
    const float* w3 = (const float*)d_in[11];
    const float* b3 = (const float*)d_in[12];
    const float* g3 = (const float*)d_in[13];
    const float* be3= (const float*)d_in[14];
    float* out = (float*)d_out;

    float *featT, *X, *W1p, *W2p, *W3p, *Y1, *Y2, *Y3;
    cudaGetSymbolAddress((void**)&featT, g_featT);
    cudaGetSymbolAddress((void**)&X,     g_X);
    cudaGetSymbolAddress((void**)&W1p,   g_W1p);
    cudaGetSymbolAddress((void**)&W2p,   g_W2p);
    cudaGetSymbolAddress((void**)&W3p,   g_W3p);
    cudaGetSymbolAddress((void**)&Y1,    g_Y1);
    cudaGetSymbolAddress((void**)&Y2,    g_Y2);
    cudaGetSymbolAddress((void**)&Y3,    g_Y3);
    float2* aff;
    cudaGetSymbolAddress((void**)&aff, g_aff);

    // prep
    transpose_kernel<<<dim3(Nn/32, Cc/32, Bb), dim3(32,8)>>>(features);
    prepw_kernel<<<128, 256>>>(w1, w2, w3);
    newxyz_kernel<<<(Bb*Mm + 255)/256, 256>>>(points_xyz, indices, out);

    // ball query
    ballquery_kernel<<<(Bb*Mm*32)/256, 256>>>(points_xyz);

    // grouped input
    buildx_kernel<<<(COLSX*32)/256, 256>>>(points_xyz);

    // layer 1
    gemm_kernel<XK, true, false><<<dim3(COLSX/128, 1), 256>>>(W1p, X, b1, aff, Y1, 128);
    stats_kernel<<<dim3(128, 8), 256>>>(Y1);
    finalize_kernel<<<1, 256>>>(g1, be1, 128);

    // layer 2 (activation of layer1 folded into the loader)
    gemm_kernel<128, false, true><<<dim3(COLSX/128, 1), 256>>>(W2p, Y1, b2, aff, Y2, 128);
    stats_kernel<<<dim3(128, 8), 256>>>(Y2);
    finalize_kernel<<<1, 256>>>(g2, be2, 128);

    // layer 3
    gemm_kernel<128, false, true><<<dim3(COLSX/128, 2), 256>>>(W3p, Y2, b3, aff, Y3, 256);
    stats_kernel<<<dim3(256, 8), 256>>>(Y3);
    finalize_kernel<<<1, 256>>>(g3, be3, 256);

    // max over K + output
    finalmax_kernel<<<(Bb*256*Mm)/256, 256>>>(out);

    (void)in_sizes; (void)n_in; (void)out_size;
}

// round 3
// speedup vs baseline: 1.8795x; 1.8795x over previous
#include <cuda_runtime.h>
#include <cuda_bf16.h>
#include <cstdint>

// Problem constants
#define Bb 4
#define Nn 16384
#define Cc 128
#define Mm 1024
#define Kk 32
#define COLSX (Bb*Mm*Kk)          // 131072
#define R2c 0.16f
#define XK 136                     // padded input-channel dim for GEMM1 (131 -> 136)
#define NBLK 1024                  // column blocks per GEMM (COLSX/128)

// -------------------- scratch (__device__ globals; no allocations) ---------
__device__ float g_featT[(size_t)Bb*Nn*Cc];        // (B,N,C) transposed features
__device__ float g_newxyz[Bb*Mm*3];
__device__ int   g_idx[Bb*Mm*Kk];
__device__ float g_X[(size_t)COLSX*XK];            // grouped input, row per col
__device__ float g_W1p[XK*128];                    // W packed [k][cout]
__device__ float g_W2p[128*128];
__device__ float g_W3p[128*256];
__device__ float g_Y1[(size_t)128*COLSX];
__device__ float g_Y2[(size_t)128*COLSX];
__device__ float g_Y3[(size_t)256*COLSX];
__device__ float2 g_part[(size_t)256*NBLK];        // per-(channel, col-block) partial sums
__device__ float2 g_aff[256];

// -------------------- helpers ---------------------------------------------
__device__ __forceinline__ unsigned long long pack2(float lo, float hi){
    unsigned long long r;
    asm("mov.b64 %0, {%1,%2};" : "=l"(r) : "f"(lo), "f"(hi));
    return r;
}
__device__ __forceinline__ float2 unpack2(unsigned long long v){
    float2 r;
    asm("mov.b64 {%0,%1}, %2;" : "=f"(r.x), "=f"(r.y) : "l"(v));
    return r;
}
__device__ __forceinline__ void fma2(unsigned long long &d, unsigned long long a, unsigned long long b){
    asm("fma.rn.f32x2 %0, %1, %2, %3;" : "=l"(d) : "l"(a), "l"(b), "l"(d));
}

// -------------------- 1. transpose features (B,C,N)->(B,N,C) ---------------
__global__ void transpose_kernel(const float* __restrict__ f){
    __shared__ float tile[32][33];
    const int b  = blockIdx.z;
    const int c0 = blockIdx.y << 5;
    const int n0 = blockIdx.x << 5;
    const int tx = threadIdx.x, ty = threadIdx.y;
    #pragma unroll
    for (int j = 0; j < 32; j += 8)
        tile[ty + j][tx] = f[((size_t)(b*Cc + c0 + ty + j))*Nn + n0 + tx];
    __syncthreads();
    #pragma unroll
    for (int j = 0; j < 32; j += 8)
        g_featT[((size_t)(b*Nn + n0 + ty + j))*Cc + c0 + tx] = tile[tx][ty + j];
}

// -------------------- 2. weight prep (transpose + pad/reorder W1) ----------
__global__ void prepw_kernel(const float* __restrict__ w1, const float* __restrict__ w2,
                             const float* __restrict__ w3){
    int e = blockIdx.x*256 + threadIdx.x;
    if (e < XK*128){
        int kk = e >> 7, o = e & 127;
        float v = 0.f;
        if (kk < 3) v = w1[o*131 + kk];
        else if (kk >= 4 && kk < 132) v = w1[o*131 + kk - 1];
        g_W1p[e] = v;                       // [kk][o]
    }
    if (e < 128*128){
        int kk = e >> 7, o = e & 127;
        g_W2p[e] = w2[o*128 + kk];
    }
    if (e < 128*256){
        int kk = e >> 8, o = e & 255;
        g_W3p[e] = w3[o*128 + kk];
    }
}

// -------------------- 3. new_xyz gather (also writes output head) ----------
__global__ void newxyz_kernel(const float* __restrict__ xyz, const int* __restrict__ indices,
                              float* __restrict__ out){
    int t = blockIdx.x*256 + threadIdx.x;
    if (t >= Bb*Mm) return;
    int b = t >> 10;
    int i = indices[t];
    const float* p = xyz + ((size_t)b*Nn + i)*3;
    float x = p[0], y = p[1], z = p[2];
    g_newxyz[t*3+0] = x; g_newxyz[t*3+1] = y; g_newxyz[t*3+2] = z;
    out[t*3+0] = x; out[t*3+1] = y; out[t*3+2] = z;
}

// -------------------- 4. ball query: 8 warps per query + ordered merge -----
// Each warp scans a 2048-point segment (early exit at 32 local hits);
// warp 0 then merges segments in index order -> identical first-k semantics.
__global__ __launch_bounds__(256) void ballquery_kernel(const float* __restrict__ xyz){
    const int q = blockIdx.x;                 // 0 .. B*M-1
    const int b = q >> 10;
    const int warp = threadIdx.x >> 5;
    const int lane = threadIdx.x & 31;
    __shared__ int cand[8][33];
    __shared__ int cnts[8];

    const float qx = g_newxyz[q*3+0];
    const float qy = g_newxyz[q*3+1];
    const float qz = g_newxyz[q*3+2];
    const float* bp = xyz + (size_t)b*Nn*3;
    const int seg0 = warp << 11;              // warp*2048

    int cnt = 0;
    for (int base = 0; base < 2048; base += 32){
        int n = seg0 + base + lane;
        float px = __ldg(bp + n*3 + 0);
        float py = __ldg(bp + n*3 + 1);
        float pz = __ldg(bp + n*3 + 2);
        float dx = __fadd_rn(qx, -px), dy = __fadd_rn(qy, -py), dz = __fadd_rn(qz, -pz);
        float d2 = __fadd_rn(__fadd_rn(__fmul_rn(dx,dx), __fmul_rn(dy,dy)), __fmul_rn(dz,dz));
        bool w = d2 < R2c;
        unsigned mask = __ballot_sync(0xffffffffu, w);
        int pre = __popc(mask & ((1u << lane) - 1u));
        if (w && cnt + pre < Kk) cand[warp][cnt + pre] = n;
        cnt += __popc(mask);
        if (cnt >= Kk) break;
    }
    if (lane == 0) cnts[warp] = cnt < Kk ? cnt : Kk;
    __syncthreads();

    if (warp == 0){
        int acc = 0, sel = -1, off = 0, first = -1;
        #pragma unroll
        for (int s = 0; s < 8; s++){
            int cs = cnts[s];
            if (sel < 0 && lane < acc + cs){ sel = s; off = lane - acc; }
            if (first < 0 && cs > 0) first = s;
            acc += cs;
        }
        int v = (sel >= 0) ? cand[sel][off]
                           : (first >= 0 ? cand[first][0] : 0);
        g_idx[q*Kk + lane] = v;
    }
}

// -------------------- 5. build grouped X (warp per column) -----------------
__global__ void buildx_kernel(const float* __restrict__ xyz){
    const int warp = (blockIdx.x*blockDim.x + threadIdx.x) >> 5;
    const int lane = threadIdx.x & 31;
    if (warp >= COLSX) return;
    const int col = warp;
    const int b = col >> 15;
    const int m = (col >> 5) & 1023;
    const int i = g_idx[col];
    float* dst = g_X + (size_t)col*XK;
    float4 f = *(const float4*)(g_featT + ((size_t)(b*Nn + i))*Cc + lane*4);
    *(float4*)(dst + 4 + lane*4) = f;
    if (lane == 0){
        const float* p = xyz + ((size_t)b*Nn + i)*3;
        const float* q = g_newxyz + (b*Mm + m)*3;
        float4 h; h.x = p[0]-q[0]; h.y = p[1]-q[1]; h.z = p[2]-q[2]; h.w = 0.f;
        *(float4*)dst = h;
        float4 zz; zz.x = zz.y = zz.z = zz.w = 0.f;
        *(float4*)(dst + 132) = zz;
    }
}

// -------------------- 6. SGEMM (f32x2 packed FMA) + fused BN partial stats -
template<int CKT, bool FROMX, bool ACT>
__global__ __launch_bounds__(256, 2)
void gemm_kernel(const float* __restrict__ Wp, const float* __restrict__ Bsrc,
                 const float* __restrict__ bias, const float2* __restrict__ aff,
                 float* __restrict__ Y, int RT)
{
    __shared__ float As[2][8][128];
    __shared__ float Bs[2][8][128];
    const int tid = threadIdx.x;
    const int tx = tid & 15, ty = tid >> 4;
    const int cb = blockIdx.x << 7;
    const int rb = blockIdx.y << 7;

    const int a_kc  = tid >> 5;
    const int a_row = (tid & 31) << 2;
    const int x_col = tid & 127;
    const int x_kh  = (tid >> 7) << 2;   // 0 or 4

    unsigned long long acc[8][4];
    #pragma unroll
    for (int i = 0; i < 8; i++)
        #pragma unroll
        for (int j = 0; j < 4; j++) acc[i][j] = 0ull;

    auto ldgA = [&](int k0) -> float4 {
        return *(const float4*)(Wp + (size_t)(k0 + a_kc)*RT + rb + a_row);
    };
    auto ldgB = [&](int k0) -> float4 {
        if (FROMX){
            return *(const float4*)(Bsrc + (size_t)(cb + x_col)*XK + k0 + x_kh);
        } else {
            float4 v = *(const float4*)(Bsrc + (size_t)(k0 + a_kc)*COLSX + cb + a_row);
            if (ACT){
                float2 af = aff[k0 + a_kc];
                v.x = fmaxf(fmaf(af.x, v.x, af.y), 0.f);
                v.y = fmaxf(fmaf(af.x, v.y, af.y), 0.f);
                v.z = fmaxf(fmaf(af.x, v.z, af.y), 0.f);
                v.w = fmaxf(fmaf(af.x, v.w, af.y), 0.f);
            }
            return v;
        }
    };
    auto stA = [&](int buf, float4 v){ *(float4*)&As[buf][a_kc][a_row] = v; };
    auto stB = [&](int buf, float4 v){
        if (FROMX){
            Bs[buf][x_kh+0][x_col] = v.x;
            Bs[buf][x_kh+1][x_col] = v.y;
            Bs[buf][x_kh+2][x_col] = v.z;
            Bs[buf][x_kh+3][x_col] = v.w;
        } else {
            *(float4*)&Bs[buf][a_kc][a_row] = v;
        }
    };

    stA(0, ldgA(0));
    stB(0, ldgB(0));
    __syncthreads();

    const int NT = CKT/8;
    #pragma unroll 1
    for (int t = 0; t < NT; ++t){
        float4 aP, bP;
        if (t + 1 < NT){ aP = ldgA((t+1)*8); bP = ldgB((t+1)*8); }
        const int buf = t & 1;
        #pragma unroll
        for (int kc = 0; kc < 8; ++kc){
            float4 a0 = *(const float4*)&As[buf][kc][ty<<3];
            float4 a1 = *(const float4*)&As[buf][kc][(ty<<3)+4];
            ulonglong2 bv0 = *(const ulonglong2*)&Bs[buf][kc][tx<<3];
            ulonglong2 bv1 = *(const ulonglong2*)&Bs[buf][kc][(tx<<3)+4];
            unsigned long long bb0 = bv0.x, bb1 = bv0.y, bb2 = bv1.x, bb3 = bv1.y;
            float av[8] = {a0.x,a0.y,a0.z,a0.w,a1.x,a1.y,a1.z,a1.w};
            #pragma unroll
            for (int i = 0; i < 8; i++){
                unsigned long long aa = pack2(av[i], av[i]);
                fma2(acc[i][0], aa, bb0);
                fma2(acc[i][1], aa, bb1);
                fma2(acc[i][2], aa, bb2);
                fma2(acc[i][3], aa, bb3);
            }
        }
        if (t + 1 < NT){ stA(buf^1, aP); stB(buf^1, bP); __syncthreads(); }
    }

    #pragma unroll
    for (int i = 0; i < 8; i++){
        int r = rb + (ty<<3) + i;
        float bv = bias[r];
        float2 p0 = unpack2(acc[i][0]);
        float2 p1 = unpack2(acc[i][1]);
        float2 p2 = unpack2(acc[i][2]);
        float2 p3 = unpack2(acc[i][3]);
        float4 o0; o0.x = p0.x+bv; o0.y = p0.y+bv; o0.z = p1.x+bv; o0.w = p1.y+bv;
        float4 o1; o1.x = p2.x+bv; o1.y = p2.y+bv; o1.z = p3.x+bv; o1.w = p3.y+bv;
        float* dst = Y + (size_t)r*COLSX + cb + (tx<<3);
        *(float4*)dst       = o0;
        *(float4*)(dst + 4) = o1;

        // fused BN partial stats (per-row sum / sumsq over this block's 128 cols)
        float s  = o0.x + o0.y + o0.z + o0.w + o1.x + o1.y + o1.z + o1.w;
        float s2 = o0.x*o0.x + o0.y*o0.y + o0.z*o0.z + o0.w*o0.w
                 + o1.x*o1.x + o1.y*o1.y + o1.z*o1.z + o1.w*o1.w;
        #pragma unroll
        for (int o = 8; o > 0; o >>= 1){
            s  += __shfl_xor_sync(0xffffffffu, s,  o, 16);
            s2 += __shfl_xor_sync(0xffffffffu, s2, o, 16);
        }
        if (tx == 0) g_part[(size_t)r*NBLK + blockIdx.x] = make_float2(s, s2);
    }
}

// -------------------- 7. finalize BN affine from partials ------------------
__global__ void finalize_kernel(const float* __restrict__ gamma, const float* __restrict__ beta){
    const int c = blockIdx.x;
    float s = 0.f, s2 = 0.f;
    for (int i = threadIdx.x; i < NBLK; i += 256){
        float2 v = g_part[(size_t)c*NBLK + i];
        s += v.x; s2 += v.y;
    }
    #pragma unroll
    for (int o = 16; o > 0; o >>= 1){
        s  += __shfl_down_sync(0xffffffffu, s,  o);
        s2 += __shfl_down_sync(0xffffffffu, s2, o);
    }
    __shared__ float rs[8], rs2[8];
    int w = threadIdx.x >> 5, l = threadIdx.x & 31;
    if (l == 0){ rs[w] = s; rs2[w] = s2; }
    __syncthreads();
    if (threadIdx.x == 0){
        float S = 0.f, S2 = 0.f;
        #pragma unroll
        for (int i = 0; i < 8; i++){ S += rs[i]; S2 += rs2[i]; }
        float inv = 1.f/(float)COLSX;
        float mu  = S*inv;
        float var = fmaxf(S2*inv - mu*mu, 0.f);
        float a = gamma[c]*rsqrtf(var + 1e-5f);
        g_aff[c] = make_float2(a, beta[c] - a*mu);
    }
}

// -------------------- 8. final affine+relu+max over K ----------------------
__global__ void finalmax_kernel(float* __restrict__ out){
    int t = blockIdx.x*256 + threadIdx.x;            // 0 .. B*256*M-1
    int m  = t & 1023;
    int co = (t >> 10) & 255;
    int b  = t >> 18;
    float2 af = g_aff[co];
    const float4* src = (const float4*)(g_Y3 + (size_t)co*COLSX) + ((size_t)(b*Mm + m))*8;
    float mx = 0.f;   // relu lower bound
    #pragma unroll
    for (int i = 0; i < 8; i++){
        float4 v = src[i];
        mx = fmaxf(mx, fmaf(af.x, v.x, af.y));
        mx = fmaxf(mx, fmaf(af.x, v.y, af.y));
        mx = fmaxf(mx, fmaf(af.x, v.z, af.y));
        mx = fmaxf(mx, fmaf(af.x, v.w, af.y));
    }
    out[Bb*Mm*3 + (((size_t)(b*256 + co)) << 10) + m] = mx;
}

// -------------------- launch ----------------------------------------------
extern "C" void kernel_launch(void* const* d_in, const int* in_sizes, int n_in,
                              void* d_out, int out_size)
{
    const float* points_xyz = (const float*)d_in[0];
    const float* features   = (const float*)d_in[1];
    const int*   indices    = (const int*)  d_in[2];
    const float* w1 = (const float*)d_in[3];
    const float* b1 = (const float*)d_in[4];
    const float* g1 = (const float*)d_in[5];
    const float* be1= (const float*)d_in[6];
    const float* w2 = (const float*)d_in[7];
    const float* b2 = (const float*)d_in[8];
    const float* g2 = (const float*)d_in[9];
    const float* be2= (const float*)d_in[10];
    const float* w3 = (const float*)d_in[11];
    const float* b3 = (const float*)d_in[12];
    const float* g3 = (const float*)d_in[13];
    const float* be3= (const float*)d_in[14];
    float* out = (float*)d_out;

    float *X, *W1p, *W2p, *W3p, *Y1, *Y2, *Y3;
    cudaGetSymbolAddress((void**)&X,     g_X);
    cudaGetSymbolAddress((void**)&W1p,   g_W1p);
    cudaGetSymbolAddress((void**)&W2p,   g_W2p);
    cudaGetSymbolAddress((void**)&W3p,   g_W3p);
    cudaGetSymbolAddress((void**)&Y1,    g_Y1);
    cudaGetSymbolAddress((void**)&Y2,    g_Y2);
    cudaGetSymbolAddress((void**)&Y3,    g_Y3);
    float2* aff;
    cudaGetSymbolAddress((void**)&aff, g_aff);

    // prep
    transpose_kernel<<<dim3(Nn/32, Cc/32, Bb), dim3(32,8)>>>(features);
    prepw_kernel<<<128, 256>>>(w1, w2, w3);
    newxyz_kernel<<<(Bb*Mm + 255)/256, 256>>>(points_xyz, indices, out);

    // ball query: 1 block (8 warps) per query
    ballquery_kernel<<<Bb*Mm, 256>>>(points_xyz);

    // grouped input
    buildx_kernel<<<(COLSX*32)/256, 256>>>(points_xyz);

    // layer 1
    gemm_kernel<XK, true, false><<<dim3(NBLK, 1), 256>>>(W1p, X, b1, aff, Y1, 128);
    finalize_kernel<<<128, 256>>>(g1, be1);

    // layer 2 (activation of layer1 folded into the loader)
    gemm_kernel<128, false, true><<<dim3(NBLK, 1), 256>>>(W2p, Y1, b2, aff, Y2, 128);
    finalize_kernel<<<128, 256>>>(g2, be2);

    // layer 3
    gemm_kernel<128, false, true><<<dim3(NBLK, 2), 256>>>(W3p, Y2, b3, aff, Y3, 256);
    finalize_kernel<<<256, 256>>>(g3, be3);

    // max over K + output
    finalmax_kernel<<<(Bb*256*Mm)/256, 256>>>(out);

    (void)in_sizes; (void)n_in; (void)out_size;
}

// round 5
// speedup vs baseline: 2.4464x; 1.3016x over previous
#include <cuda_runtime.h>
#include <cuda_bf16.h>
#include <cstdint>

// Problem constants
#define Bb 4
#define Nn 16384
#define Cc 128
#define Mm 1024
#define Kk 32
#define COLSX (Bb*Mm*Kk)          // 131072
#define R2c 0.16f
#define XK 160                     // padded input-channel dim for GEMM1 (131 -> 160)
#define NBLK 1024                  // column tiles per GEMM (COLSX/128)

// -------------------- scratch (__device__ globals; no allocations) ---------
__device__ float  g_featT[(size_t)Bb*Nn*Cc];       // (B,N,C)
__device__ float4 g_xyz4[(size_t)Bb*Nn];           // packed xyz
__device__ float  g_newxyz[Bb*Mm*3];
__device__ int    g_idx[Bb*Mm*Kk];
__device__ float  g_X [(size_t)COLSX*XK];          // [col][160] K-major
__device__ float  g_W1p[128*XK];                   // [cout][160]
__device__ float  g_Y1[(size_t)COLSX*128];         // [col][cout]
__device__ float  g_Y2[(size_t)COLSX*128];
__device__ float  g_Y3[(size_t)COLSX*256];
__device__ float2 g_part[(size_t)256*NBLK];
__device__ float2 g_aff[256];

// -------------------- helpers ----------------------------------------------
__device__ __forceinline__ uint32_t smem_u32(const void* p){
    uint32_t a;
    asm("{ .reg .u64 t; cvta.to.shared.u64 t, %1; cvt.u32.u64 %0, t; }" : "=r"(a) : "l"(p));
    return a;
}
__device__ __forceinline__ void ldm4(uint32_t* r, uint32_t addr){
    asm volatile("ldmatrix.sync.aligned.m8n8.x4.shared.b16 {%0,%1,%2,%3}, [%4];"
        : "=r"(r[0]), "=r"(r[1]), "=r"(r[2]), "=r"(r[3]) : "r"(addr));
}
__device__ __forceinline__ void mma_bf16(float* d, const uint32_t* a, const uint32_t* b){
    asm volatile("mma.sync.aligned.m16n8k16.row.col.f32.bf16.bf16.f32 "
        "{%0,%1,%2,%3}, {%4,%5,%6,%7}, {%8,%9}, {%0,%1,%2,%3};"
        : "+f"(d[0]), "+f"(d[1]), "+f"(d[2]), "+f"(d[3])
        : "r"(a[0]), "r"(a[1]), "r"(a[2]), "r"(a[3]), "r"(b[0]), "r"(b[1]));
}
// split 8 floats into hi/lo bf16 quads (hi4 = 8 bf16, lo4 = 8 bf16)
__device__ __forceinline__ void cvt8(const float* f, uint4& H, uint4& L){
    uint32_t hh[4], ll[4];
    #pragma unroll
    for (int i = 0; i < 4; i++){
        __nv_bfloat162 h = __floats2bfloat162_rn(f[2*i], f[2*i+1]);
        float r0 = f[2*i]   - __low2float(h);
        float r1 = f[2*i+1] - __high2float(h);
        __nv_bfloat162 l = __floats2bfloat162_rn(r0, r1);
        hh[i] = *(uint32_t*)&h;
        ll[i] = *(uint32_t*)&l;
    }
    H = make_uint4(hh[0], hh[1], hh[2], hh[3]);
    L = make_uint4(ll[0], ll[1], ll[2], ll[3]);
}

// -------------------- 1. transpose features (B,C,N)->(B,N,C) ---------------
__global__ void transpose_kernel(const float* __restrict__ f){
    __shared__ float tile[32][33];
    const int b  = blockIdx.z;
    const int c0 = blockIdx.y << 5;
    const int n0 = blockIdx.x << 5;
    const int tx = threadIdx.x, ty = threadIdx.y;
    #pragma unroll
    for (int j = 0; j < 32; j += 8)
        tile[ty + j][tx] = f[((size_t)(b*Cc + c0 + ty + j))*Nn + n0 + tx];
    __syncthreads();
    #pragma unroll
    for (int j = 0; j < 32; j += 8)
        g_featT[((size_t)(b*Nn + n0 + ty + j))*Cc + c0 + tx] = tile[tx][ty + j];
}

// -------------------- 1b. pack xyz into float4 -----------------------------
__global__ void xyz4_kernel(const float* __restrict__ xyz){
    int t = blockIdx.x*256 + threadIdx.x;
    if (t >= Bb*Nn) return;
    float4 v; v.x = xyz[t*3+0]; v.y = xyz[t*3+1]; v.z = xyz[t*3+2]; v.w = 0.f;
    g_xyz4[t] = v;
}

// -------------------- 2. W1 pad --------------------------------------------
__global__ void prepw_kernel(const float* __restrict__ w1){
    int e = blockIdx.x*256 + threadIdx.x;
    if (e >= 128*XK) return;
    int o = e / XK, k = e % XK;
    g_W1p[e] = (k < 131) ? w1[o*131 + k] : 0.f;
}

// -------------------- 3. new_xyz gather ------------------------------------
__global__ void newxyz_kernel(const float* __restrict__ xyz, const int* __restrict__ indices,
                              float* __restrict__ out){
    int t = blockIdx.x*256 + threadIdx.x;
    if (t >= Bb*Mm) return;
    int b = t >> 10;
    int i = indices[t];
    const float* p = xyz + ((size_t)b*Nn + i)*3;
    float x = p[0], y = p[1], z = p[2];
    g_newxyz[t*3+0] = x; g_newxyz[t*3+1] = y; g_newxyz[t*3+2] = z;
    out[t*3+0] = x; out[t*3+1] = y; out[t*3+2] = z;
}

// -------------------- 4. ball query: 8 warps/query + ordered merge ---------
__global__ __launch_bounds__(256) void ballquery_kernel(){
    const int q = blockIdx.x;
    const int b = q >> 10;
    const int warp = threadIdx.x >> 5;
    const int lane = threadIdx.x & 31;
    __shared__ int cand[8][33];
    __shared__ int cnts[8];

    const float qx = g_newxyz[q*3+0];
    const float qy = g_newxyz[q*3+1];
    const float qz = g_newxyz[q*3+2];
    const float4* bp = g_xyz4 + (size_t)b*Nn;
    const int seg0 = warp << 11;

    int cnt = 0;
    for (int base = 0; base < 2048; base += 32){
        int n = seg0 + base + lane;
        float4 p = __ldg(bp + n);
        float dx = __fadd_rn(qx, -p.x), dy = __fadd_rn(qy, -p.y), dz = __fadd_rn(qz, -p.z);
        float d2 = __fadd_rn(__fadd_rn(__fmul_rn(dx,dx), __fmul_rn(dy,dy)), __fmul_rn(dz,dz));
        bool w = d2 < R2c;
        unsigned mask = __ballot_sync(0xffffffffu, w);
        int pre = __popc(mask & ((1u << lane) - 1u));
        if (w && cnt + pre < Kk) cand[warp][cnt + pre] = n;
        cnt += __popc(mask);
        if (cnt >= Kk) break;
    }
    if (lane == 0) cnts[warp] = cnt < Kk ? cnt : Kk;
    __syncthreads();

    if (warp == 0){
        int acc = 0, sel = -1, off = 0, first = -1;
        #pragma unroll
        for (int s = 0; s < 8; s++){
            int cs = cnts[s];
            if (sel < 0 && lane < acc + cs){ sel = s; off = lane - acc; }
            if (first < 0 && cs > 0) first = s;
            acc += cs;
        }
        int v = (sel >= 0) ? cand[sel][off]
                           : (first >= 0 ? cand[first][0] : 0);
        g_idx[q*Kk + lane] = v;
    }
}

// -------------------- 5. build grouped X [col][160] ------------------------
__global__ void buildx_kernel(){
    const int warp = (blockIdx.x*blockDim.x + threadIdx.x) >> 5;
    const int lane = threadIdx.x & 31;
    if (warp >= COLSX) return;
    const int col = warp;
    const int b = col >> 15;
    const int m = (col >> 5) & 1023;
    const int i = g_idx[col];
    float* dst = g_X + (size_t)col*XK;
    float4 f = *(const float4*)(g_featT + ((size_t)(b*Nn + i))*Cc + lane*4);
    dst[3 + lane*4 + 0] = f.x;
    dst[3 + lane*4 + 1] = f.y;
    dst[3 + lane*4 + 2] = f.z;
    dst[3 + lane*4 + 3] = f.w;
    if (lane < 29) dst[131 + lane] = 0.f;
    if (lane == 0){
        float4 p = g_xyz4[(size_t)b*Nn + i];
        const float* q = g_newxyz + (b*Mm + m)*3;
        dst[0] = p.x - q[0]; dst[1] = p.y - q[1]; dst[2] = p.z - q[2];
    }
}

// -------------------- 6. mma.sync bf16-split GEMM --------------------------
// C[128 m(cout)][128 n(cols)] = A[128,K]*B[128,K]^T,  A,B f32 K-major in gmem.
// Split x = hi + lo (bf16); D += Ah*Bh + Ah*Bl + Al*Bh  (fp32 accum).
// smem row (per matrix row): 128B = chunks 0-3 hi (32 k bf16), 4-7 lo;
// 16B chunk c stored at phys c ^ (row&7)  -> ldmatrix conflict-free.
#define OFF_AFF  0
#define OFF_PART 1024
#define OFF_SA   4096
#define OFF_SB   (4096 + 2*16384)
#define OFF_C    4096
#define CPITCH   132
#define SMEM_GEMM (4096 + 128*CPITCH*4)   // 71680 (covers compute: 4096+64K)

template<int KA, int NC, int KSOUT, bool ACT>
__global__ __launch_bounds__(256, 2)
void mma_gemm(const float* __restrict__ Asrc, const float* __restrict__ Bsrc,
              const float* __restrict__ bias, float* __restrict__ Y)
{
    extern __shared__ char smem[];
    const uint32_t sb = smem_u32(smem);
    const int tid = threadIdx.x, wid = tid >> 5, lane = tid & 31;
    const int cb = blockIdx.x << 7;
    const int rb = blockIdx.y << 7;
    const int m0 = (wid >> 1) << 5;     // warp m-base (32 rows)
    const int n0w = (wid & 1) << 6;     // warp n-base (64 cols)

    float* afs = (float*)(smem + OFF_AFF);     // float2[128] as floats
    if (ACT && tid < 128) ((float2*)afs)[tid] = g_aff[tid];
    if (ACT) __syncthreads();

    float acc[2][8][4];
    #pragma unroll
    for (int a = 0; a < 2; a++)
        #pragma unroll
        for (int b2 = 0; b2 < 8; b2++)
            #pragma unroll
            for (int c = 0; c < 4; c++) acc[a][b2][c] = 0.f;

    auto CVST = [&](int c){
        const int k0 = c*32;
        char* SAb = smem + OFF_SA + ((c & 1) << 14);
        char* SBb = smem + OFF_SB + ((c & 1) << 14);
        #pragma unroll
        for (int s = tid; s < 512; s += 256){
            const int m = s >> 2, oct = s & 3;
            const float* src = Asrc + (size_t)(rb + m)*KA + k0 + oct*8;
            float f[8];
            *(float4*)&f[0] = __ldg((const float4*)src);
            *(float4*)&f[4] = __ldg((const float4*)(src + 4));
            uint4 H, L; cvt8(f, H, L);
            const uint32_t ro = (uint32_t)m << 7;
            *(uint4*)(SAb + ro + (uint32_t)((oct       ^ (m & 7)) << 4)) = H;
            *(uint4*)(SAb + ro + (uint32_t)(((oct + 4) ^ (m & 7)) << 4)) = L;
        }
        #pragma unroll
        for (int s = tid; s < 512; s += 256){
            const int n = s >> 2, oct = s & 3;
            const float* src = Bsrc + (size_t)(cb + n)*KA + k0 + oct*8;
            float f[8];
            *(float4*)&f[0] = __ldg((const float4*)src);
            *(float4*)&f[4] = __ldg((const float4*)(src + 4));
            if (ACT){
                #pragma unroll
                for (int i = 0; i < 8; i++){
                    const int k = k0 + oct*8 + i;
                    f[i] = fmaxf(fmaf(afs[2*k], f[i], afs[2*k+1]), 0.f);
                }
            }
            uint4 H, L; cvt8(f, H, L);
            const uint32_t ro = (uint32_t)n << 7;
            *(uint4*)(SBb + ro + (uint32_t)((oct       ^ (n & 7)) << 4)) = H;
            *(uint4*)(SBb + ro + (uint32_t)(((oct + 4) ^ (n & 7)) << 4)) = L;
        }
    };

    CVST(0);
    __syncthreads();

    const int arow = m0 + (lane & 15);
    const int asel = lane >> 4;                     // k-half for A ldmatrix
    const int nrow0 = n0w + ((lane >> 4) << 3) + (lane & 7);
    const int bsel = (lane >> 3) & 1;               // k-half for B ldmatrix

    #pragma unroll 1
    for (int c = 0; c < NC; ++c){
        const uint32_t sbA = sb + OFF_SA + ((c & 1) << 14);
        const uint32_t sbB = sb + OFF_SB + ((c & 1) << 14);
        #pragma unroll
        for (int t = 0; t < 2; t++){
            uint32_t ah[2][4], al[2][4];
            #pragma unroll
            for (int mi = 0; mi < 2; mi++){
                const int row = arow + mi*16;
                const uint32_t base = sbA + ((uint32_t)row << 7);
                const int ch = 2*t + asel;
                ldm4(ah[mi], base + (uint32_t)(((ch    ) ^ (row & 7)) << 4));
                ldm4(al[mi], base + (uint32_t)(((ch + 4) ^ (row & 7)) << 4));
            }
            #pragma unroll
            for (int j = 0; j < 4; j++){
                const int n = nrow0 + j*16;
                const uint32_t nb = sbB + ((uint32_t)n << 7);
                const int ch = 2*t + bsel;
                uint32_t bh[4], bl[4];
                ldm4(bh, nb + (uint32_t)(((ch    ) ^ (n & 7)) << 4));
                mma_bf16(acc[0][2*j],   ah[0], bh + 0);
                mma_bf16(acc[0][2*j+1], ah[0], bh + 2);
                mma_bf16(acc[1][2*j],   ah[1], bh + 0);
                mma_bf16(acc[1][2*j+1], ah[1], bh + 2);
                mma_bf16(acc[0][2*j],   al[0], bh + 0);
                mma_bf16(acc[0][2*j+1], al[0], bh + 2);
                mma_bf16(acc[1][2*j],   al[1], bh + 0);
                mma_bf16(acc[1][2*j+1], al[1], bh + 2);
                ldm4(bl, nb + (uint32_t)(((ch + 4) ^ (n & 7)) << 4));
                mma_bf16(acc[0][2*j],   ah[0], bl + 0);
                mma_bf16(acc[0][2*j+1], ah[0], bl + 2);
                mma_bf16(acc[1][2*j],   ah[1], bl + 0);
                mma_bf16(acc[1][2*j+1], ah[1], bl + 2);
            }
        }
        if (c + 1 < NC) CVST(c + 1);
        __syncthreads();
    }

    // ---------------- epilogue: bias + BN partials + transpose store -------
    float* C = (float*)(smem + OFF_C);
    float2* P = (float2*)(smem + OFF_PART);
    const int l4 = lane >> 2, lc = (lane & 3) << 1;
    float sr[4] = {0,0,0,0}, s2r[4] = {0,0,0,0};
    #pragma unroll
    for (int mi = 0; mi < 2; mi++){
        const int r0 = m0 + mi*16 + l4;
        const float bv0 = bias[rb + r0];
        const float bv1 = bias[rb + r0 + 8];
        #pragma unroll
        for (int ni = 0; ni < 8; ni++){
            const int n = n0w + ni*8 + lc;
            float v0 = acc[mi][ni][0] + bv0, v1 = acc[mi][ni][1] + bv0;
            float v2 = acc[mi][ni][2] + bv1, v3 = acc[mi][ni][3] + bv1;
            *(float2*)&C[(size_t)r0*CPITCH + n]       = make_float2(v0, v1);
            *(float2*)&C[(size_t)(r0+8)*CPITCH + n]   = make_float2(v2, v3);
            sr[2*mi]   += v0 + v1;  s2r[2*mi]   += v0*v0 + v1*v1;
            sr[2*mi+1] += v2 + v3;  s2r[2*mi+1] += v2*v2 + v3*v3;
        }
    }
    #pragma unroll
    for (int o = 1; o <= 2; o <<= 1){
        #pragma unroll
        for (int i = 0; i < 4; i++){
            sr[i]  += __shfl_xor_sync(0xffffffffu, sr[i],  o);
            s2r[i] += __shfl_xor_sync(0xffffffffu, s2r[i], o);
        }
    }
    if ((lane & 3) == 0){
        P[wid*32 + l4]      = make_float2(sr[0], s2r[0]);
        P[wid*32 + l4 + 8]  = make_float2(sr[1], s2r[1]);
        P[wid*32 + l4 + 16] = make_float2(sr[2], s2r[2]);
        P[wid*32 + l4 + 24] = make_float2(sr[3], s2r[3]);
    }
    __syncthreads();
    if (tid < 128){
        const int m = tid, lr = m & 31, w0 = (m >> 5) << 1;
        float2 p0 = P[w0*32 + lr], p1 = P[(w0+1)*32 + lr];
        g_part[(size_t)(rb + m)*NBLK + blockIdx.x] = make_float2(p0.x + p1.x, p0.y + p1.y);
    }
    {
        const int n = tid >> 1, hf = tid & 1;
        float* dst = Y + (size_t)(cb + n)*KSOUT + rb + hf*64;
        #pragma unroll
        for (int i = 0; i < 16; i++){
            float4 v;
            v.x = C[(size_t)(hf*64 + i*4 + 0)*CPITCH + n];
            v.y = C[(size_t)(hf*64 + i*4 + 1)*CPITCH + n];
            v.z = C[(size_t)(hf*64 + i*4 + 2)*CPITCH + n];
            v.w = C[(size_t)(hf*64 + i*4 + 3)*CPITCH + n];
            ((float4*)dst)[i] = v;
        }
    }
}

// -------------------- 7. finalize BN affine --------------------------------
__global__ void finalize_kernel(const float* __restrict__ gamma, const float* __restrict__ beta){
    const int c = blockIdx.x;
    float s = 0.f, s2 = 0.f;
    for (int i = threadIdx.x; i < NBLK; i += 256){
        float2 v = g_part[(size_t)c*NBLK + i];
        s += v.x; s2 += v.y;
    }
    #pragma unroll
    for (int o = 16; o > 0; o >>= 1){
        s  += __shfl_down_sync(0xffffffffu, s,  o);
        s2 += __shfl_down_sync(0xffffffffu, s2, o);
    }
    __shared__ float rs[8], rs2[8];
    int w = threadIdx.x >> 5, l = threadIdx.x & 31;
    if (l == 0){ rs[w] = s; rs2[w] = s2; }
    __syncthreads();
    if (threadIdx.x == 0){
        float S = 0.f, S2 = 0.f;
        #pragma unroll
        for (int i = 0; i < 8; i++){ S += rs[i]; S2 += rs2[i]; }
        float inv = 1.f/(float)COLSX;
        float mu  = S*inv;
        float var = fmaxf(S2*inv - mu*mu, 0.f);
        float a = gamma[c]*rsqrtf(var + 1e-5f);
        g_aff[c] = make_float2(a, beta[c] - a*mu);
    }
}

// -------------------- 8. final affine+relu+max over K ----------------------
__global__ __launch_bounds__(256) void finalmax_kernel(float* __restrict__ out){
    const int bm = blockIdx.x;             // 0..4095 = b*1024+m
    const int b = bm >> 10, m = bm & 1023;
    const int co = threadIdx.x;
    const float2 af = g_aff[co];
    const float* base = g_Y3 + (size_t)bm*32*256;
    float mx = 0.f;
    #pragma unroll 8
    for (int j = 0; j < 32; j++){
        float v = __ldg(base + j*256 + co);
        mx = fmaxf(mx, fmaf(af.x, v, af.y));
    }
    out[Bb*Mm*3 + (((size_t)(b*256 + co)) << 10) + m] = mx;
}

// -------------------- launch ----------------------------------------------
extern "C" void kernel_launch(void* const* d_in, const int* in_sizes, int n_in,
                              void* d_out, int out_size)
{
    const float* points_xyz = (const float*)d_in[0];
    const float* features   = (const float*)d_in[1];
    const int*   indices    = (const int*)  d_in[2];
    const float* w1 = (const float*)d_in[3];
    const float* b1 = (const float*)d_in[4];
    const float* g1 = (const float*)d_in[5];
    const float* be1= (const float*)d_in[6];
    const float* w2 = (const float*)d_in[7];
    const float* b2 = (const float*)d_in[8];
    const float* g2 = (const float*)d_in[9];
    const float* be2= (const float*)d_in[10];
    const float* w3 = (const float*)d_in[11];
    const float* b3 = (const float*)d_in[12];
    const float* g3 = (const float*)d_in[13];
    const float* be3= (const float*)d_in[14];
    float* out = (float*)d_out;

    float *X, *W1p, *Y1, *Y2, *Y3;
    cudaGetSymbolAddress((void**)&X,   g_X);
    cudaGetSymbolAddress((void**)&W1p, g_W1p);
    cudaGetSymbolAddress((void**)&Y1,  g_Y1);
    cudaGetSymbolAddress((void**)&Y2,  g_Y2);
    cudaGetSymbolAddress((void**)&Y3,  g_Y3);

    cudaFuncSetAttribute(mma_gemm<XK,  5, 128, false>, cudaFuncAttributeMaxDynamicSharedMemorySize, SMEM_GEMM);
    cudaFuncSetAttribute(mma_gemm<128, 4, 128, true >, cudaFuncAttributeMaxDynamicSharedMemorySize, SMEM_GEMM);
    cudaFuncSetAttribute(mma_gemm<128, 4, 256, true >, cudaFuncAttributeMaxDynamicSharedMemorySize, SMEM_GEMM);

    // prep
    transpose_kernel<<<dim3(Nn/32, Cc/32, Bb), dim3(32,8)>>>(features);
    xyz4_kernel<<<(Bb*Nn + 255)/256, 256>>>(points_xyz);
    prepw_kernel<<<(128*XK + 255)/256, 256>>>(w1);
    newxyz_kernel<<<(Bb*Mm + 255)/256, 256>>>(points_xyz, indices, out);

    // ball query
    ballquery_kernel<<<Bb*Mm, 256>>>();

    // grouped input
    buildx_kernel<<<(COLSX*32)/256, 256>>>();

    // layer 1
    mma_gemm<XK, 5, 128, false><<<dim3(NBLK, 1), 256, SMEM_GEMM>>>(W1p, X, b1, Y1);
    finalize_kernel<<<128, 256>>>(g1, be1);

    // layer 2 (activation of layer1 folded into the loader)
    mma_gemm<128, 4, 128, true><<<dim3(NBLK, 1), 256, SMEM_GEMM>>>(w2, Y1, b2, Y2);
    finalize_kernel<<<128, 256>>>(g2, be2);

    // layer 3
    mma_gemm<128, 4, 256, true><<<dim3(NBLK, 2), 256, SMEM_GEMM>>>(w3, Y2, b3, Y3);
    finalize_kernel<<<256, 256>>>(g3, be3);

    // max over K + output
    finalmax_kernel<<<Bb*Mm, 256>>>(out);

    (void)in_sizes; (void)n_in; (void)out_size;
}

// round 6
// speedup vs baseline: 3.0011x; 1.2267x over previous
#include <cuda_runtime.h>
#include <cuda_bf16.h>
#include <cstdint>

// Problem constants
#define Bb 4
#define Nn 16384
#define Cc 128
#define Mm 1024
#define Kk 32
#define COLSX (Bb*Mm*Kk)          // 131072
#define R2c 0.16f
#define XK 160                     // padded input-channel dim for GEMM1 (131 -> 160)
#define NBLK 1024                  // column tiles per GEMM (COLSX/128)

// -------------------- scratch (__device__ globals; no allocations) ---------
__device__ float  g_featT[(size_t)Bb*Nn*Cc];       // (B,N,C)
__device__ float4 g_xyz4[(size_t)Bb*Nn];           // packed xyz
__device__ float  g_newxyz[Bb*Mm*3];
__device__ int    g_idx[Bb*Mm*Kk];
__device__ float  g_W1p[128*XK];                   // [cout][160] permuted: feat|xyz|pad
__device__ float  g_Y1[(size_t)COLSX*128];         // [col][cout]
__device__ float  g_Y2[(size_t)COLSX*128];
__device__ float2 g_mm[(size_t)Bb*Mm*256];         // [bm][cout] (max,min) over K
__device__ float2 g_part[(size_t)256*NBLK];
__device__ float2 g_aff[256];

// -------------------- helpers ----------------------------------------------
__device__ __forceinline__ uint32_t smem_u32(const void* p){
    uint32_t a;
    asm("{ .reg .u64 t; cvta.to.shared.u64 t, %1; cvt.u32.u64 %0, t; }" : "=r"(a) : "l"(p));
    return a;
}
__device__ __forceinline__ void ldm4(uint32_t* r, uint32_t addr){
    asm volatile("ldmatrix.sync.aligned.m8n8.x4.shared.b16 {%0,%1,%2,%3}, [%4];"
        : "=r"(r[0]), "=r"(r[1]), "=r"(r[2]), "=r"(r[3]) : "r"(addr));
}
__device__ __forceinline__ void mma_bf16(float* d, const uint32_t* a, const uint32_t* b){
    asm volatile("mma.sync.aligned.m16n8k16.row.col.f32.bf16.bf16.f32 "
        "{%0,%1,%2,%3}, {%4,%5,%6,%7}, {%8,%9}, {%0,%1,%2,%3};"
        : "+f"(d[0]), "+f"(d[1]), "+f"(d[2]), "+f"(d[3])
        : "r"(a[0]), "r"(a[1]), "r"(a[2]), "r"(a[3]), "r"(b[0]), "r"(b[1]));
}
// split 8 floats into hi/lo bf16 quads
__device__ __forceinline__ void cvt8(const float* f, uint4& H, uint4& L){
    uint32_t hh[4], ll[4];
    #pragma unroll
    for (int i = 0; i < 4; i++){
        __nv_bfloat162 h = __floats2bfloat162_rn(f[2*i], f[2*i+1]);
        float r0 = f[2*i]   - __low2float(h);
        float r1 = f[2*i+1] - __high2float(h);
        __nv_bfloat162 l = __floats2bfloat162_rn(r0, r1);
        hh[i] = *(uint32_t*)&h;
        ll[i] = *(uint32_t*)&l;
    }
    H = make_uint4(hh[0], hh[1], hh[2], hh[3]);
    L = make_uint4(ll[0], ll[1], ll[2], ll[3]);
}

// -------------------- 1. transpose features (B,C,N)->(B,N,C) ---------------
__global__ void transpose_kernel(const float* __restrict__ f){
    __shared__ float tile[32][33];
    const int b  = blockIdx.z;
    const int c0 = blockIdx.y << 5;
    const int n0 = blockIdx.x << 5;
    const int tx = threadIdx.x, ty = threadIdx.y;
    #pragma unroll
    for (int j = 0; j < 32; j += 8)
        tile[ty + j][tx] = f[((size_t)(b*Cc + c0 + ty + j))*Nn + n0 + tx];
    __syncthreads();
    #pragma unroll
    for (int j = 0; j < 32; j += 8)
        g_featT[((size_t)(b*Nn + n0 + ty + j))*Cc + c0 + tx] = tile[tx][ty + j];
}

// -------------------- 1b. pack xyz into float4 -----------------------------
__global__ void xyz4_kernel(const float* __restrict__ xyz){
    int t = blockIdx.x*256 + threadIdx.x;
    if (t >= Bb*Nn) return;
    float4 v; v.x = xyz[t*3+0]; v.y = xyz[t*3+1]; v.z = xyz[t*3+2]; v.w = 0.f;
    g_xyz4[t] = v;
}

// -------------------- 2. W1 pad + permute (feat first, xyz at 128) ---------
__global__ void prepw_kernel(const float* __restrict__ w1){
    int e = blockIdx.x*256 + threadIdx.x;
    if (e >= 128*XK) return;
    int o = e / XK, k = e % XK;
    float v = 0.f;
    if (k < 128)       v = w1[o*131 + 3 + k];     // feature channels
    else if (k < 131)  v = w1[o*131 + (k - 128)]; // xyz channels
    g_W1p[e] = v;
}

// -------------------- 3. new_xyz gather ------------------------------------
__global__ void newxyz_kernel(const float* __restrict__ xyz, const int* __restrict__ indices,
                              float* __restrict__ out){
    int t = blockIdx.x*256 + threadIdx.x;
    if (t >= Bb*Mm) return;
    int b = t >> 10;
    int i = indices[t];
    const float* p = xyz + ((size_t)b*Nn + i)*3;
    float x = p[0], y = p[1], z = p[2];
    g_newxyz[t*3+0] = x; g_newxyz[t*3+1] = y; g_newxyz[t*3+2] = z;
    out[t*3+0] = x; out[t*3+1] = y; out[t*3+2] = z;
}

// -------------------- 4. ball query: 8 warps/query + ordered merge ---------
__global__ __launch_bounds__(256) void ballquery_kernel(){
    const int q = blockIdx.x;
    const int b = q >> 10;
    const int warp = threadIdx.x >> 5;
    const int lane = threadIdx.x & 31;
    __shared__ int cand[8][33];
    __shared__ int cnts[8];

    const float qx = g_newxyz[q*3+0];
    const float qy = g_newxyz[q*3+1];
    const float qz = g_newxyz[q*3+2];
    const float4* bp = g_xyz4 + (size_t)b*Nn;
    const int seg0 = warp << 11;

    int cnt = 0;
    for (int base = 0; base < 2048; base += 32){
        int n = seg0 + base + lane;
        float4 p = __ldg(bp + n);
        float dx = __fadd_rn(qx, -p.x), dy = __fadd_rn(qy, -p.y), dz = __fadd_rn(qz, -p.z);
        float d2 = __fadd_rn(__fadd_rn(__fmul_rn(dx,dx), __fmul_rn(dy,dy)), __fmul_rn(dz,dz));
        bool w = d2 < R2c;
        unsigned mask = __ballot_sync(0xffffffffu, w);
        int pre = __popc(mask & ((1u << lane) - 1u));
        if (w && cnt + pre < Kk) cand[warp][cnt + pre] = n;
        cnt += __popc(mask);
        if (cnt >= Kk) break;
    }
    if (lane == 0) cnts[warp] = cnt < Kk ? cnt : Kk;
    __syncthreads();

    if (warp == 0){
        int acc = 0, sel = -1, off = 0, first = -1;
        #pragma unroll
        for (int s = 0; s < 8; s++){
            int cs = cnts[s];
            if (sel < 0 && lane < acc + cs){ sel = s; off = lane - acc; }
            if (first < 0 && cs > 0) first = s;
            acc += cs;
        }
        int v = (sel >= 0) ? cand[sel][off]
                           : (first >= 0 ? cand[first][0] : 0);
        g_idx[q*Kk + lane] = v;
    }
}

// -------------------- 5. mma.sync bf16-split GEMM --------------------------
// C[128 m(cout)][128 n(cols)] = A[128,K]*B[128,K]^T.
// GATHER: B columns come from g_featT[g_idx[col]] (+ xyz_rel at k=128..130).
// FINAL : no Y store; per (cout, k-group) max/min over K=32 -> g_mm.
#define OFF_AFF  0
#define OFF_PART 1024
#define OFF_IDX  3072
#define OFF_XYZ  4096
#define OFF_SA   8192
#define OFF_SB   (8192 + 2*16384)
#define OFF_C    8192
#define CPITCH   132
#define SMEM_GEMM (8192 + 128*CPITCH*4)   // 75776

template<int KA, int NC, int KSOUT, bool ACT, bool GATHER, bool FINAL>
__global__ __launch_bounds__(256, 2)
void mma_gemm(const float* __restrict__ Asrc, const float* __restrict__ Bsrc,
              const float* __restrict__ bias, float* __restrict__ Y)
{
    extern __shared__ char smem[];
    const uint32_t sb = smem_u32(smem);
    const int tid = threadIdx.x, wid = tid >> 5, lane = tid & 31;
    const int cb = blockIdx.x << 7;
    const int rb = blockIdx.y << 7;
    const int m0 = (wid >> 1) << 5;
    const int n0w = (wid & 1) << 6;

    float* afs   = (float*)(smem + OFF_AFF);
    int*   sidx  = (int*)(smem + OFF_IDX);
    float4* sxyz = (float4*)(smem + OFF_XYZ);
    const size_t bBase = (size_t)(cb >> 15)*Nn;

    if (ACT && tid < 128) ((float2*)afs)[tid] = g_aff[tid];
    if (GATHER && tid < 128){
        int i = g_idx[cb + tid];
        sidx[tid] = i;
        float4 p = g_xyz4[bBase + i];
        const int bm = (cb + tid) >> 5;           // b*1024 + m
        const float* q = g_newxyz + (size_t)bm*3;
        float4 r; r.x = p.x - q[0]; r.y = p.y - q[1]; r.z = p.z - q[2]; r.w = 0.f;
        sxyz[tid] = r;
    }
    if (ACT || GATHER) __syncthreads();

    float acc[2][8][4];
    #pragma unroll
    for (int a = 0; a < 2; a++)
        #pragma unroll
        for (int b2 = 0; b2 < 8; b2++)
            #pragma unroll
            for (int c = 0; c < 4; c++) acc[a][b2][c] = 0.f;

    auto CVST = [&](int c){
        const int k0 = c*32;
        char* SAb = smem + OFF_SA + ((c & 1) << 14);
        char* SBb = smem + OFF_SB + ((c & 1) << 14);
        #pragma unroll
        for (int s = tid; s < 512; s += 256){
            const int m = s >> 2, oct = s & 3;
            const float* src = Asrc + (size_t)(rb + m)*KA + k0 + oct*8;
            float f[8];
            *(float4*)&f[0] = __ldg((const float4*)src);
            *(float4*)&f[4] = __ldg((const float4*)(src + 4));
            uint4 H, L; cvt8(f, H, L);
            const uint32_t ro = (uint32_t)m << 7;
            *(uint4*)(SAb + ro + (uint32_t)((oct       ^ (m & 7)) << 4)) = H;
            *(uint4*)(SAb + ro + (uint32_t)(((oct + 4) ^ (m & 7)) << 4)) = L;
        }
        #pragma unroll
        for (int s = tid; s < 512; s += 256){
            const int n = s >> 2, oct = s & 3;
            float f[8];
            if (GATHER){
                if (c < 4){
                    const float* src = g_featT + ((bBase + (size_t)sidx[n]) << 7) + k0 + oct*8;
                    *(float4*)&f[0] = __ldg((const float4*)src);
                    *(float4*)&f[4] = __ldg((const float4*)(src + 4));
                } else {
                    #pragma unroll
                    for (int i = 0; i < 8; i++) f[i] = 0.f;
                    if (oct == 0){ float4 xr = sxyz[n]; f[0] = xr.x; f[1] = xr.y; f[2] = xr.z; }
                }
            } else {
                const float* src = Bsrc + (size_t)(cb + n)*KA + k0 + oct*8;
                *(float4*)&f[0] = __ldg((const float4*)src);
                *(float4*)&f[4] = __ldg((const float4*)(src + 4));
                if (ACT){
                    #pragma unroll
                    for (int i = 0; i < 8; i++){
                        const int k = k0 + oct*8 + i;
                        f[i] = fmaxf(fmaf(afs[2*k], f[i], afs[2*k+1]), 0.f);
                    }
                }
            }
            uint4 H, L; cvt8(f, H, L);
            const uint32_t ro = (uint32_t)n << 7;
            *(uint4*)(SBb + ro + (uint32_t)((oct       ^ (n & 7)) << 4)) = H;
            *(uint4*)(SBb + ro + (uint32_t)(((oct + 4) ^ (n & 7)) << 4)) = L;
        }
    };

    CVST(0);
    __syncthreads();

    const int arow = m0 + (lane & 15);
    const int asel = lane >> 4;
    const int nrow0 = n0w + ((lane >> 4) << 3) + (lane & 7);
    const int bsel = (lane >> 3) & 1;

    #pragma unroll 1
    for (int c = 0; c < NC; ++c){
        const uint32_t sbA = sb + OFF_SA + ((c & 1) << 14);
        const uint32_t sbB = sb + OFF_SB + ((c & 1) << 14);
        #pragma unroll
        for (int t = 0; t < 2; t++){
            uint32_t ah[2][4], al[2][4];
            #pragma unroll
            for (int mi = 0; mi < 2; mi++){
                const int row = arow + mi*16;
                const uint32_t base = sbA + ((uint32_t)row << 7);
                const int ch = 2*t + asel;
                ldm4(ah[mi], base + (uint32_t)(((ch    ) ^ (row & 7)) << 4));
                ldm4(al[mi], base + (uint32_t)(((ch + 4) ^ (row & 7)) << 4));
            }
            #pragma unroll
            for (int j = 0; j < 4; j++){
                const int n = nrow0 + j*16;
                const uint32_t nb = sbB + ((uint32_t)n << 7);
                const int ch = 2*t + bsel;
                uint32_t bh[4], bl[4];
                ldm4(bh, nb + (uint32_t)(((ch    ) ^ (n & 7)) << 4));
                mma_bf16(acc[0][2*j],   ah[0], bh + 0);
                mma_bf16(acc[0][2*j+1], ah[0], bh + 2);
                mma_bf16(acc[1][2*j],   ah[1], bh + 0);
                mma_bf16(acc[1][2*j+1], ah[1], bh + 2);
                mma_bf16(acc[0][2*j],   al[0], bh + 0);
                mma_bf16(acc[0][2*j+1], al[0], bh + 2);
                mma_bf16(acc[1][2*j],   al[1], bh + 0);
                mma_bf16(acc[1][2*j+1], al[1], bh + 2);
                ldm4(bl, nb + (uint32_t)(((ch + 4) ^ (n & 7)) << 4));
                mma_bf16(acc[0][2*j],   ah[0], bl + 0);
                mma_bf16(acc[0][2*j+1], ah[0], bl + 2);
                mma_bf16(acc[1][2*j],   ah[1], bl + 0);
                mma_bf16(acc[1][2*j+1], ah[1], bl + 2);
            }
        }
        if (c + 1 < NC) CVST(c + 1);
        __syncthreads();
    }

    // ---------------- epilogue: bias + BN partials + store/reduce ----------
    float* C = (float*)(smem + OFF_C);
    float2* P = (float2*)(smem + OFF_PART);
    const int l4 = lane >> 2, lc = (lane & 3) << 1;
    float sr[4] = {0,0,0,0}, s2r[4] = {0,0,0,0};
    #pragma unroll
    for (int mi = 0; mi < 2; mi++){
        const int r0 = m0 + mi*16 + l4;
        const float bv0 = bias[rb + r0];
        const float bv1 = bias[rb + r0 + 8];
        #pragma unroll
        for (int ni = 0; ni < 8; ni++){
            const int n = n0w + ni*8 + lc;
            float v0 = acc[mi][ni][0] + bv0, v1 = acc[mi][ni][1] + bv0;
            float v2 = acc[mi][ni][2] + bv1, v3 = acc[mi][ni][3] + bv1;
            *(float2*)&C[(size_t)r0*CPITCH + n]       = make_float2(v0, v1);
            *(float2*)&C[(size_t)(r0+8)*CPITCH + n]   = make_float2(v2, v3);
            sr[2*mi]   += v0 + v1;  s2r[2*mi]   += v0*v0 + v1*v1;
            sr[2*mi+1] += v2 + v3;  s2r[2*mi+1] += v2*v2 + v3*v3;
        }
    }
    #pragma unroll
    for (int o = 1; o <= 2; o <<= 1){
        #pragma unroll
        for (int i = 0; i < 4; i++){
            sr[i]  += __shfl_xor_sync(0xffffffffu, sr[i],  o);
            s2r[i] += __shfl_xor_sync(0xffffffffu, s2r[i], o);
        }
    }
    if ((lane & 3) == 0){
        P[wid*32 + l4]      = make_float2(sr[0], s2r[0]);
        P[wid*32 + l4 + 8]  = make_float2(sr[1], s2r[1]);
        P[wid*32 + l4 + 16] = make_float2(sr[2], s2r[2]);
        P[wid*32 + l4 + 24] = make_float2(sr[3], s2r[3]);
    }
    __syncthreads();
    if (tid < 128){
        const int m = tid, lr = m & 31, w0 = (m >> 5) << 1;
        float2 p0 = P[w0*32 + lr], p1 = P[(w0+1)*32 + lr];
        g_part[(size_t)(rb + m)*NBLK + blockIdx.x] = make_float2(p0.x + p1.x, p0.y + p1.y);
    }
    if (FINAL){
        // per (cout row, k-group of 32 cols): max/min over K
        const int row = tid >> 1;
        #pragma unroll
        for (int gg = 0; gg < 2; gg++){
            const int g = ((tid & 1) << 1) + gg;
            const float* src = C + (size_t)row*CPITCH + g*32;
            float mx = -3.4e38f, mn = 3.4e38f;
            #pragma unroll
            for (int k = 0; k < 32; k++){
                float v = src[k];
                mx = fmaxf(mx, v); mn = fminf(mn, v);
            }
            g_mm[(size_t)((cb >> 5) + g)*256 + rb + row] = make_float2(mx, mn);
        }
    } else {
        const int n = tid >> 1, hf = tid & 1;
        float* dst = Y + (size_t)(cb + n)*KSOUT + rb + hf*64;
        #pragma unroll
        for (int i = 0; i < 16; i++){
            float4 v;
            v.x = C[(size_t)(hf*64 + i*4 + 0)*CPITCH + n];
            v.y = C[(size_t)(hf*64 + i*4 + 1)*CPITCH + n];
            v.z = C[(size_t)(hf*64 + i*4 + 2)*CPITCH + n];
            v.w = C[(size_t)(hf*64 + i*4 + 3)*CPITCH + n];
            ((float4*)dst)[i] = v;
        }
    }
}

// -------------------- 6. finalize BN affine --------------------------------
__global__ void finalize_kernel(const float* __restrict__ gamma, const float* __restrict__ beta){
    const int c = blockIdx.x;
    float s = 0.f, s2 = 0.f;
    for (int i = threadIdx.x; i < NBLK; i += 256){
        float2 v = g_part[(size_t)c*NBLK + i];
        s += v.x; s2 += v.y;
    }
    #pragma unroll
    for (int o = 16; o > 0; o >>= 1){
        s  += __shfl_down_sync(0xffffffffu, s,  o);
        s2 += __shfl_down_sync(0xffffffffu, s2, o);
    }
    __shared__ float rs[8], rs2[8];
    int w = threadIdx.x >> 5, l = threadIdx.x & 31;
    if (l == 0){ rs[w] = s; rs2[w] = s2; }
    __syncthreads();
    if (threadIdx.x == 0){
        float S = 0.f, S2 = 0.f;
        #pragma unroll
        for (int i = 0; i < 8; i++){ S += rs[i]; S2 += rs2[i]; }
        float inv = 1.f/(float)COLSX;
        float mu  = S*inv;
        float var = fmaxf(S2*inv - mu*mu, 0.f);
        float a = gamma[c]*rsqrtf(var + 1e-5f);
        g_aff[c] = make_float2(a, beta[c] - a*mu);
    }
}

// -------------------- 7. final: affine + relu on (max|min) -----------------
__global__ __launch_bounds__(256) void finalmax_kernel(float* __restrict__ out){
    const int bm = blockIdx.x;             // b*1024 + m
    const int b = bm >> 10, m = bm & 1023;
    const int co = threadIdx.x;
    const float2 af = g_aff[co];
    const float2 mm = g_mm[(size_t)bm*256 + co];
    const float v = (af.x >= 0.f) ? mm.x : mm.y;
    out[Bb*Mm*3 + (((size_t)(b*256 + co)) << 10) + m] = fmaxf(fmaf(af.x, v, af.y), 0.f);
}

// -------------------- launch ----------------------------------------------
extern "C" void kernel_launch(void* const* d_in, const int* in_sizes, int n_in,
                              void* d_out, int out_size)
{
    const float* points_xyz = (const float*)d_in[0];
    const float* features   = (const float*)d_in[1];
    const int*   indices    = (const int*)  d_in[2];
    const float* w1 = (const float*)d_in[3];
    const float* b1 = (const float*)d_in[4];
    const float* g1 = (const float*)d_in[5];
    const float* be1= (const float*)d_in[6];
    const float* w2 = (const float*)d_in[7];
    const float* b2 = (const float*)d_in[8];
    const float* g2 = (const float*)d_in[9];
    const float* be2= (const float*)d_in[10];
    const float* w3 = (const float*)d_in[11];
    const float* b3 = (const float*)d_in[12];
    const float* g3 = (const float*)d_in[13];
    const float* be3= (const float*)d_in[14];
    float* out = (float*)d_out;

    float *W1p, *Y1, *Y2;
    cudaGetSymbolAddress((void**)&W1p, g_W1p);
    cudaGetSymbolAddress((void**)&Y1,  g_Y1);
    cudaGetSymbolAddress((void**)&Y2,  g_Y2);

    cudaFuncSetAttribute(mma_gemm<XK,  5, 128, false, true,  false>, cudaFuncAttributeMaxDynamicSharedMemorySize, SMEM_GEMM);
    cudaFuncSetAttribute(mma_gemm<128, 4, 128, true,  false, false>, cudaFuncAttributeMaxDynamicSharedMemorySize, SMEM_GEMM);
    cudaFuncSetAttribute(mma_gemm<128, 4, 256, true,  false, true >, cudaFuncAttributeMaxDynamicSharedMemorySize, SMEM_GEMM);

    // prep
    transpose_kernel<<<dim3(Nn/32, Cc/32, Bb), dim3(32,8)>>>(features);
    xyz4_kernel<<<(Bb*Nn + 255)/256, 256>>>(points_xyz);
    prepw_kernel<<<(128*XK + 255)/256, 256>>>(w1);
    newxyz_kernel<<<(Bb*Mm + 255)/256, 256>>>(points_xyz, indices, out);

    // ball query
    ballquery_kernel<<<Bb*Mm, 256>>>();

    // layer 1 (gather fused)
    mma_gemm<XK, 5, 128, false, true, false><<<dim3(NBLK, 1), 256, SMEM_GEMM>>>(W1p, nullptr, b1, Y1);
    finalize_kernel<<<128, 256>>>(g1, be1);

    // layer 2 (layer1 activation folded into loader)
    mma_gemm<128, 4, 128, true, false, false><<<dim3(NBLK, 1), 256, SMEM_GEMM>>>(w2, Y1, b2, Y2);
    finalize_kernel<<<128, 256>>>(g2, be2);

    // layer 3 (K-max/min fused into epilogue)
    mma_gemm<128, 4, 256, true, false, true><<<dim3(NBLK, 2), 256, SMEM_GEMM>>>(w3, Y2, b3, nullptr);
    finalize_kernel<<<256, 256>>>(g3, be3);

    // final: affine + relu on reduced extrema
    finalmax_kernel<<<Bb*Mm, 256>>>(out);

    (void)in_sizes; (void)n_in; (void)out_size;
}